// round 2
// baseline (speedup 1.0000x reference)
#include <cuda_runtime.h>
#include <math.h>

#define S_   4
#define B_   64
#define K_   3
#define T_   8
#define FPX  96
#define DPX  28
#define CPX  69
#define NPX  4761     // 69*69
#define H_   512
#define SB   256      // S_*B_
#define FRPIX 9216    // 96*96

// ---------------- scratch (device globals; no allocation allowed) ----------------
__device__ float g_frame[SB * FRPIX];        // residual frame_left, 9.4 MB
__device__ float g_scores[SB * NPX];         // post-softmax scores, 4.9 MB
__device__ float g_hpart[8][SB * H_];        // split-K partials for GEMM1, 4 MB
__device__ float g_h[SB * H_];               // relu(scores@W1 + b1)
__device__ float g_hm[SB * H_];              // [hm | hs] (256 cols each)
__device__ float g_z[SB * 2];                // z_where for recon

// ---------------- init: frame_left = frames[:, :, timestep] ----------------
__global__ void init_frame_kernel(const float* __restrict__ frames,
                                  const int* __restrict__ ts_p) {
    int idx = blockIdx.x * 256 + threadIdx.x;
    if (idx >= SB * FRPIX) return;
    int ts = *ts_p;
    int p = idx / FRPIX, off = idx % FRPIX;
    g_frame[idx] = frames[(size_t)(p * T_ + ts) * FRPIX + off];
}

// ---------------- fused conv (VALID 96x96 (*) 28x28 -> 69x69) + softmax ----------------
// smem layout (floats): sf[96*97+40] frame (row stride 97, conflict-free),
//                       sk[784] kernel, ssc[4761] scores, red[32]
#define SF_STRIDE 97
#define CONV_SMEM_FLOATS (96 * 97 + 40 + 784 + 4761 + 32)

__global__ __launch_bounds__(256) void conv_softmax_kernel(
    const float* __restrict__ ck, int k) {
    extern __shared__ float smem[];
    float* sf  = smem;
    float* sk  = sf + 96 * 97 + 40;
    float* ssc = sk + 784;
    float* red = ssc + NPX;

    int p = blockIdx.x;
    int tid = threadIdx.x;

    const float* gf = g_frame + (size_t)p * FRPIX;
    for (int i = tid; i < FRPIX; i += 256) {
        int r = i / FPX, c = i - r * FPX;
        sf[r * SF_STRIDE + c] = gf[i];
    }
    const float* gk = ck + ((size_t)p * K_ + k) * 784;
    for (int i = tid; i < 784; i += 256) sk[i] = gk[i];
    __syncthreads();

    // warp covers 8 rows x 4 colblocks; lane = rsub + 8*csub -> smem bank-clean
    int warp = tid >> 5, lane = tid & 31;
    int rsub = lane & 7, csub = lane >> 3;
    for (int wt = warp; wt < 27; wt += 8) {
        int rg = wt / 3, cg = wt - rg * 3;
        int r  = rg * 8 + rsub;       // output row (0..71, valid <69)
        int cb = cg * 4 + csub;       // colblock (0..11, valid <9)
        if (r < CPX && cb < 9) {
            int x0 = cb * 8;
            float acc[8] = {0.f,0.f,0.f,0.f,0.f,0.f,0.f,0.f};
            for (int ky = 0; ky < DPX; ky++) {
                const float* fr = sf + (r + ky) * SF_STRIDE + x0;
                const float* kr = sk + ky * DPX;
                float win[35];
                #pragma unroll
                for (int i = 0; i < 35; i++) win[i] = fr[i];
                #pragma unroll
                for (int kx = 0; kx < DPX; kx++) {
                    float kv = kr[kx];
                    #pragma unroll
                    for (int j = 0; j < 8; j++)
                        acc[j] = fmaf(win[kx + j], kv, acc[j]);
                }
            }
            int nc = min(8, CPX - x0);
            for (int j = 0; j < nc; j++) ssc[r * CPX + x0 + j] = acc[j];
        }
    }
    __syncthreads();

    // --- block softmax over 4761 ---
    float lm = -3.4e38f;
    for (int i = tid; i < NPX; i += 256) lm = fmaxf(lm, ssc[i]);
    #pragma unroll
    for (int o = 16; o; o >>= 1) lm = fmaxf(lm, __shfl_xor_sync(0xffffffffu, lm, o));
    if (lane == 0) red[warp] = lm;
    __syncthreads();
    float M = red[0];
    #pragma unroll
    for (int w = 1; w < 8; w++) M = fmaxf(M, red[w]);
    __syncthreads();

    float ls = 0.f;
    for (int i = tid; i < NPX; i += 256) {
        float e = expf(ssc[i] - M);
        ssc[i] = e;
        ls += e;
    }
    #pragma unroll
    for (int o = 16; o; o >>= 1) ls += __shfl_xor_sync(0xffffffffu, ls, o);
    if (lane == 0) red[warp] = ls;
    __syncthreads();
    float tot = 0.f;
    #pragma unroll
    for (int w = 0; w < 8; w++) tot += red[w];
    float inv = 1.f / tot;

    float* gs = g_scores + (size_t)p * NPX;
    for (int i = tid; i < NPX; i += 256) gs[i] = ssc[i] * inv;
}

// ---------------- GEMM1: scores(256x4761) @ W1(4761x512), split-K=8 ----------------
__global__ __launch_bounds__(256) void gemm1_kernel(const float* __restrict__ W1) {
    __shared__ float As[16][68];
    __shared__ float Bs[16][68];
    int m0 = blockIdx.x * 64, n0 = blockIdx.y * 64;
    int kbeg = blockIdx.z * 596;
    int kend = min(NPX, kbeg + 596);
    int tid = threadIdx.x;
    int tx = tid & 15, ty = tid >> 4;
    int alk = tid & 15, alm = tid >> 4;   // A load: k in lane, m strided
    int bln = tid & 63, blk = tid >> 6;   // B load: n in lane, k strided

    float acc[4][4] = {};
    for (int kk = kbeg; kk < kend; kk += 16) {
        #pragma unroll
        for (int i = 0; i < 4; i++) {
            int kg = kk + alk;
            int m  = alm + i * 16;
            As[alk][m] = (kg < kend) ? g_scores[(size_t)(m0 + m) * NPX + kg] : 0.f;
        }
        #pragma unroll
        for (int i = 0; i < 4; i++) {
            int kg = kk + blk + i * 4;
            Bs[blk + i * 4][bln] = (kg < kend) ? W1[(size_t)kg * H_ + n0 + bln] : 0.f;
        }
        __syncthreads();
        #pragma unroll
        for (int q = 0; q < 16; q++) {
            float a[4], b[4];
            *(float4*)a = *(const float4*)&As[q][ty * 4];
            *(float4*)b = *(const float4*)&Bs[q][tx * 4];
            #pragma unroll
            for (int i = 0; i < 4; i++)
                #pragma unroll
                for (int j = 0; j < 4; j++)
                    acc[i][j] = fmaf(a[i], b[j], acc[i][j]);
        }
        __syncthreads();
    }
    float* outp = g_hpart[blockIdx.z];
    #pragma unroll
    for (int i = 0; i < 4; i++)
        #pragma unroll
        for (int j = 0; j < 4; j++)
            outp[(size_t)(m0 + ty * 4 + i) * H_ + n0 + tx * 4 + j] = acc[i][j];
}

// ---------------- reduce split-K partials + bias + relu ----------------
__global__ void reduce_relu_kernel(const float* __restrict__ b1) {
    int idx = blockIdx.x * 256 + threadIdx.x;   // < 256*512
    float s = b1[idx & (H_ - 1)];
    #pragma unroll
    for (int r = 0; r < 8; r++) s += g_hpart[r][idx];
    g_h[idx] = fmaxf(s, 0.f);
}

// ---------------- GEMM2: h(256x512) @ [Wm1 | Ws1](512x512) + bias + relu ----------------
__global__ __launch_bounds__(256) void gemm2_kernel(
    const float* __restrict__ Wm1, const float* __restrict__ bm1,
    const float* __restrict__ Ws1, const float* __restrict__ bs1) {
    __shared__ float As[16][68];
    __shared__ float Bs[16][68];
    int m0 = blockIdx.x * 64, n0 = blockIdx.y * 64;
    const float* Wb   = (n0 < 256) ? Wm1 : Ws1;
    const float* bias = (n0 < 256) ? bm1 : bs1;
    int nc0 = n0 & 255;

    int tid = threadIdx.x;
    int tx = tid & 15, ty = tid >> 4;
    int alk = tid & 15, alm = tid >> 4;
    int bln = tid & 63, blk = tid >> 6;

    float acc[4][4] = {};
    for (int kk = 0; kk < H_; kk += 16) {
        #pragma unroll
        for (int i = 0; i < 4; i++) {
            int m = alm + i * 16;
            As[alk][m] = g_h[(size_t)(m0 + m) * H_ + kk + alk];
        }
        #pragma unroll
        for (int i = 0; i < 4; i++) {
            int kg = kk + blk + i * 4;
            Bs[blk + i * 4][bln] = Wb[(size_t)kg * 256 + nc0 + bln];
        }
        __syncthreads();
        #pragma unroll
        for (int q = 0; q < 16; q++) {
            float a[4], b[4];
            *(float4*)a = *(const float4*)&As[q][ty * 4];
            *(float4*)b = *(const float4*)&Bs[q][tx * 4];
            #pragma unroll
            for (int i = 0; i < 4; i++)
                #pragma unroll
                for (int j = 0; j < 4; j++)
                    acc[i][j] = fmaf(a[i], b[j], acc[i][j]);
        }
        __syncthreads();
    }
    #pragma unroll
    for (int i = 0; i < 4; i++)
        #pragma unroll
        for (int j = 0; j < 4; j++) {
            float v = acc[i][j] + bias[nc0 + tx * 4 + j];
            g_hm[(size_t)(m0 + ty * 4 + i) * H_ + n0 + tx * 4 + j] = fmaxf(v, 0.f);
        }
}

// ---------------- heads: mean = tanh(hm@Wm2+bm2), std = exp(hs@Ws2+bs2), z ----------------
__global__ void head_kernel(const float* __restrict__ Wm2, const float* __restrict__ bm2,
                            const float* __restrict__ Ws2, const float* __restrict__ bs2,
                            const float* __restrict__ eps, float* __restrict__ out, int k) {
    __shared__ float sh[H_];
    __shared__ float sred[8];
    int p = blockIdx.x, tid = threadIdx.x;
    for (int i = tid; i < H_; i += 64) sh[i] = g_hm[(size_t)p * H_ + i];
    __syncthreads();

    float pm0 = 0, pm1 = 0, ps0 = 0, ps1 = 0;
    for (int i = tid; i < 256; i += 64) {
        float hm = sh[i], hs = sh[256 + i];
        pm0 = fmaf(hm, Wm2[2 * i],     pm0);
        pm1 = fmaf(hm, Wm2[2 * i + 1], pm1);
        ps0 = fmaf(hs, Ws2[2 * i],     ps0);
        ps1 = fmaf(hs, Ws2[2 * i + 1], ps1);
    }
    #pragma unroll
    for (int o = 16; o; o >>= 1) {
        pm0 += __shfl_down_sync(0xffffffffu, pm0, o);
        pm1 += __shfl_down_sync(0xffffffffu, pm1, o);
        ps0 += __shfl_down_sync(0xffffffffu, ps0, o);
        ps1 += __shfl_down_sync(0xffffffffu, ps1, o);
    }
    int warp = tid >> 5, lane = tid & 31;
    if (lane == 0) {
        sred[warp * 4 + 0] = pm0; sred[warp * 4 + 1] = pm1;
        sred[warp * 4 + 2] = ps0; sred[warp * 4 + 3] = ps1;
    }
    __syncthreads();
    if (tid == 0) {
        float m0 = sred[0] + sred[4], m1 = sred[1] + sred[5];
        float s0 = sred[2] + sred[6], s1 = sred[3] + sred[7];
        float mean0 = tanhf(m0 + bm2[0]), mean1 = tanhf(m1 + bm2[1]);
        float std0  = expf(s0 + bs2[0]),  std1  = expf(s1 + bs2[1]);
        float e0 = eps[(p * K_ + k) * 2], e1 = eps[(p * K_ + k) * 2 + 1];
        float z0 = fmaf(std0, e0, mean0), z1 = fmaf(std1, e1, mean1);
        int o = p * 6 + k * 2;
        out[o] = mean0;        out[o + 1] = mean1;          // q_mean
        out[1536 + o] = std0;  out[1536 + o + 1] = std1;    // q_std
        out[3072 + o] = z0;    out[3072 + o + 1] = z1;      // z_where
        g_z[p * 2] = z0; g_z[p * 2 + 1] = z1;
    }
}

// ---------------- recon: bilinear digit placement, subtract from frame_left ----------------
__global__ void recon_kernel(const float* __restrict__ ck, int k) {
    __shared__ float dig[784];
    __shared__ float wx0[96], wx1[96], wy0[96], wy1[96];
    __shared__ int   ix0[96], ix1[96], iy0[96], iy1[96];
    int p = blockIdx.x, tid = threadIdx.x;
    const float* gk = ck + ((size_t)p * K_ + k) * 784;
    for (int i = tid; i < 784; i += 256) dig[i] = gk[i];
    float z0 = g_z[p * 2], z1 = g_z[p * 2 + 1];

    if (tid < 192) {
        int j = tid % 96;
        float zw = (tid < 96) ? z0 : z1;
        const float scale = (float)(96.0 / 28.0);
        float oc = (2.f * j + 1.f) / 96.f - 1.f;
        float pp = ((scale * (oc - zw) + 1.f) * 28.f - 1.f) * 0.5f;
        float p0 = floorf(pp);
        float f  = pp - p0;
        int i0 = (int)p0, i1 = i0 + 1;
        float w0 = (i0 >= 0 && i0 < DPX) ? 1.f - f : 0.f;
        float w1 = (i1 >= 0 && i1 < DPX) ? f : 0.f;
        i0 = min(max(i0, 0), DPX - 1);
        i1 = min(max(i1, 0), DPX - 1);
        if (tid < 96) { wx0[j] = w0; wx1[j] = w1; ix0[j] = i0; ix1[j] = i1; }
        else          { wy0[j] = w0; wy1[j] = w1; iy0[j] = i0; iy1[j] = i1; }
    }
    __syncthreads();

    float* fl = g_frame + (size_t)p * FRPIX;
    for (int idx = tid; idx < FRPIX; idx += 256) {
        int i = idx / 96, j = idx - i * 96;
        float a = wy0[i] * dig[iy0[i] * DPX + ix0[j]] + wy1[i] * dig[iy1[i] * DPX + ix0[j]];
        float b = wy0[i] * dig[iy0[i] * DPX + ix1[j]] + wy1[i] * dig[iy1[i] * DPX + ix1[j]];
        fl[idx] -= (wx0[j] * a + wx1[j] * b);
    }
}

// ---------------- launch ----------------
extern "C" void kernel_launch(void* const* d_in, const int* in_sizes, int n_in,
                              void* d_out, int out_size) {
    const float* frames = (const float*)d_in[0];
    const float* ck     = (const float*)d_in[1];
    const float* eps    = (const float*)d_in[2];
    const float* W1     = (const float*)d_in[3];
    const float* b1     = (const float*)d_in[4];
    const float* Wm1    = (const float*)d_in[5];
    const float* bm1    = (const float*)d_in[6];
    const float* Wm2    = (const float*)d_in[7];
    const float* bm2    = (const float*)d_in[8];
    const float* Ws1    = (const float*)d_in[9];
    const float* bs1    = (const float*)d_in[10];
    const float* Ws2    = (const float*)d_in[11];
    const float* bs2    = (const float*)d_in[12];
    const int*   ts     = (const int*)d_in[13];
    float* out = (float*)d_out;

    const int convSmem = CONV_SMEM_FLOATS * (int)sizeof(float);  // ~59.7 KB
    cudaFuncSetAttribute(conv_softmax_kernel,
                         cudaFuncAttributeMaxDynamicSharedMemorySize, convSmem);

    init_frame_kernel<<<(SB * FRPIX + 255) / 256, 256>>>(frames, ts);

    for (int k = 0; k < K_; k++) {
        conv_softmax_kernel<<<SB, 256, convSmem>>>(ck, k);
        gemm1_kernel<<<dim3(4, 8, 8), 256>>>(W1);
        reduce_relu_kernel<<<(SB * H_) / 256, 256>>>(b1);
        gemm2_kernel<<<dim3(4, 8), 256>>>(Wm1, bm1, Ws1, bs1);
        head_kernel<<<SB, 64>>>(Wm2, bm2, Ws2, bs2, eps, out, k);
        recon_kernel<<<SB, 256>>>(ck, k);
    }
}

// round 3
// speedup vs baseline: 1.4134x; 1.4134x over previous
#include <cuda_runtime.h>
#include <math.h>

#define S_   4
#define B_   64
#define K_   3
#define T_   8
#define FPX  96
#define DPX  28
#define CPX  69
#define NPX  4761     // 69*69
#define NPXP 4768     // padded to multiple of 16
#define H_   512
#define SB   256      // S_*B_
#define FRPIX 9216    // 96*96

// ---------------- scratch (device globals; no allocation allowed) ----------------
__device__ float g_frame[SB * FRPIX];        // residual frame_left
__device__ float g_scores[SB * NPXP];        // post-softmax scores (padded rows, tail zeros)
__device__ float g_hpart[9][SB * H_];        // split-K partials for GEMM1
__device__ float g_h[SB * H_];               // relu(scores@W1 + b1)
__device__ float g_h2part[4][SB * H_];       // split-K partials for GEMM2
__device__ float g_z[SB * 2];                // z_where for recon

// ---------------- init: frame_left = frames[:, :, timestep] ----------------
__global__ void init_frame_kernel(const float* __restrict__ frames,
                                  const int* __restrict__ ts_p) {
    int idx = blockIdx.x * 256 + threadIdx.x;
    if (idx >= SB * FRPIX) return;
    int ts = *ts_p;
    int p = idx / FRPIX, off = idx % FRPIX;
    g_frame[idx] = frames[(size_t)(p * T_ + ts) * FRPIX + off];
}

// ---------------- fused conv (VALID 96x96 (*) 28x28 -> 69x69) + softmax ----------------
#define SF_STRIDE 97
#define CONV_SMEM_FLOATS (96 * 97 + 40 + 784 + NPX + 32)

__global__ __launch_bounds__(256) void conv_softmax_kernel(
    const float* __restrict__ ck, int k) {
    extern __shared__ float smem[];
    float* sf  = smem;
    float* sk  = sf + 96 * 97 + 40;
    float* ssc = sk + 784;
    float* red = ssc + NPX;

    int p = blockIdx.x;
    int tid = threadIdx.x;

    const float* gf = g_frame + (size_t)p * FRPIX;
    for (int i = tid; i < FRPIX; i += 256) {
        int r = i / FPX, c = i - r * FPX;
        sf[r * SF_STRIDE + c] = gf[i];
    }
    const float* gk = ck + ((size_t)p * K_ + k) * 784;
    for (int i = tid; i < 784; i += 256) sk[i] = gk[i];
    __syncthreads();

    // flat units: u = cb*69 + r  (column-block-major: consecutive lanes -> consecutive rows)
    #pragma unroll
    for (int rnd = 0; rnd < 3; rnd++) {
        int u = tid + rnd * 256;
        if (u < 621) {
            int cb = u / 69;          // 0..8
            int r  = u - cb * 69;     // 0..68
            int x0 = cb * 8;
            float acc[8] = {0.f,0.f,0.f,0.f,0.f,0.f,0.f,0.f};
            for (int ky = 0; ky < DPX; ky++) {
                const float* fr = sf + (r + ky) * SF_STRIDE + x0;
                const float* kr = sk + ky * DPX;
                float win[35];
                #pragma unroll
                for (int i = 0; i < 35; i++) win[i] = fr[i];
                #pragma unroll
                for (int kx = 0; kx < DPX; kx++) {
                    float kv = kr[kx];
                    #pragma unroll
                    for (int j = 0; j < 8; j++)
                        acc[j] = fmaf(win[kx + j], kv, acc[j]);
                }
            }
            int nc = min(8, CPX - x0);
            for (int j = 0; j < nc; j++) ssc[r * CPX + x0 + j] = acc[j];
        }
    }
    __syncthreads();

    // --- block softmax over 4761 ---
    int warp = tid >> 5, lane = tid & 31;
    float lm = -3.4e38f;
    for (int i = tid; i < NPX; i += 256) lm = fmaxf(lm, ssc[i]);
    #pragma unroll
    for (int o = 16; o; o >>= 1) lm = fmaxf(lm, __shfl_xor_sync(0xffffffffu, lm, o));
    if (lane == 0) red[warp] = lm;
    __syncthreads();
    float M = red[0];
    #pragma unroll
    for (int w = 1; w < 8; w++) M = fmaxf(M, red[w]);
    __syncthreads();

    float ls = 0.f;
    for (int i = tid; i < NPX; i += 256) {
        float e = expf(ssc[i] - M);
        ssc[i] = e;
        ls += e;
    }
    #pragma unroll
    for (int o = 16; o; o >>= 1) ls += __shfl_xor_sync(0xffffffffu, ls, o);
    if (lane == 0) red[warp] = ls;
    __syncthreads();
    float tot = 0.f;
    #pragma unroll
    for (int w = 0; w < 8; w++) tot += red[w];
    float inv = 1.f / tot;

    float* gs = g_scores + (size_t)p * NPXP;
    for (int i = tid; i < NPX; i += 256) gs[i] = ssc[i] * inv;
    if (tid < NPXP - NPX) gs[NPX + tid] = 0.f;   // zero pad tail
}

// ---------------- GEMM1: scores(256x4761) @ W1(4761x512), 128x64 tile, 8x8/thread,
//                  double-buffered, splitK=9 ----------------
__global__ __launch_bounds__(128) void gemm1_kernel(const float* __restrict__ W1) {
    __shared__ float As[2][16][132];
    __shared__ float Bs[2][16][68];
    int m0 = blockIdx.x * 128, n0 = blockIdx.y * 64;
    int z  = blockIdx.z;
    int kbeg = z * 544;
    int kend = min(NPXP, kbeg + 544);          // all chunks multiples of 16
    int nIter = (kend - kbeg) >> 4;

    int tid = threadIdx.x;
    int tx = tid & 7, ty = tid >> 3;
    int bkr = tid >> 4, bnc = tid & 15;        // B: krow base (0..7), n-float4 (0..15)

    const float* aRow = g_scores + (size_t)(m0 + tid) * NPXP;

    float4 areg[4], breg[2];

    // prologue: load tile 0
    {
        int kt = kbeg;
        #pragma unroll
        for (int i = 0; i < 4; i++)
            areg[i] = *(const float4*)(aRow + kt + i * 4);
        #pragma unroll
        for (int i = 0; i < 2; i++) {
            int kg = kt + bkr + i * 8;
            breg[i] = (kg < NPX) ? *(const float4*)(W1 + (size_t)kg * H_ + n0 + bnc * 4)
                                 : make_float4(0.f, 0.f, 0.f, 0.f);
        }
        #pragma unroll
        for (int i = 0; i < 4; i++) {
            As[0][i * 4 + 0][tid] = areg[i].x;
            As[0][i * 4 + 1][tid] = areg[i].y;
            As[0][i * 4 + 2][tid] = areg[i].z;
            As[0][i * 4 + 3][tid] = areg[i].w;
        }
        #pragma unroll
        for (int i = 0; i < 2; i++)
            *(float4*)&Bs[0][bkr + i * 8][bnc * 4] = breg[i];
    }
    __syncthreads();

    float acc[8][8] = {};
    for (int it = 0; it < nIter; it++) {
        int buf = it & 1;
        if (it + 1 < nIter) {
            int kt = kbeg + (it + 1) * 16;
            #pragma unroll
            for (int i = 0; i < 4; i++)
                areg[i] = *(const float4*)(aRow + kt + i * 4);
            #pragma unroll
            for (int i = 0; i < 2; i++) {
                int kg = kt + bkr + i * 8;
                breg[i] = (kg < NPX) ? *(const float4*)(W1 + (size_t)kg * H_ + n0 + bnc * 4)
                                     : make_float4(0.f, 0.f, 0.f, 0.f);
            }
        }
        #pragma unroll
        for (int q = 0; q < 16; q++) {
            float a[8], b[8];
            *(float4*)&a[0] = *(const float4*)&As[buf][q][ty * 8];
            *(float4*)&a[4] = *(const float4*)&As[buf][q][ty * 8 + 4];
            *(float4*)&b[0] = *(const float4*)&Bs[buf][q][tx * 8];
            *(float4*)&b[4] = *(const float4*)&Bs[buf][q][tx * 8 + 4];
            #pragma unroll
            for (int i = 0; i < 8; i++)
                #pragma unroll
                for (int j = 0; j < 8; j++)
                    acc[i][j] = fmaf(a[i], b[j], acc[i][j]);
        }
        if (it + 1 < nIter) {
            int nb = buf ^ 1;
            #pragma unroll
            for (int i = 0; i < 4; i++) {
                As[nb][i * 4 + 0][tid] = areg[i].x;
                As[nb][i * 4 + 1][tid] = areg[i].y;
                As[nb][i * 4 + 2][tid] = areg[i].z;
                As[nb][i * 4 + 3][tid] = areg[i].w;
            }
            #pragma unroll
            for (int i = 0; i < 2; i++)
                *(float4*)&Bs[nb][bkr + i * 8][bnc * 4] = breg[i];
        }
        __syncthreads();
    }

    float* outp = g_hpart[z];
    #pragma unroll
    for (int i = 0; i < 8; i++) {
        float* row = outp + (size_t)(m0 + ty * 8 + i) * H_ + n0 + tx * 8;
        *(float4*)row       = *(float4*)&acc[i][0];
        *(float4*)(row + 4) = *(float4*)&acc[i][4];
    }
}

// ---------------- reduce split-K partials + bias + relu (float4) ----------------
__global__ void reduce_relu_kernel(const float* __restrict__ b1) {
    int idx4 = blockIdx.x * 256 + threadIdx.x;      // < 32768
    float4 s = ((const float4*)b1)[idx4 & 127];
    #pragma unroll
    for (int r = 0; r < 9; r++) {
        float4 v = ((const float4*)g_hpart[r])[idx4];
        s.x += v.x; s.y += v.y; s.z += v.z; s.w += v.w;
    }
    s.x = fmaxf(s.x, 0.f); s.y = fmaxf(s.y, 0.f);
    s.z = fmaxf(s.z, 0.f); s.w = fmaxf(s.w, 0.f);
    ((float4*)g_h)[idx4] = s;
}

// ---------------- GEMM2: h(256x512) @ [Wm1 | Ws1](512x512), splitK=4 ----------------
__global__ __launch_bounds__(256) void gemm2_kernel(
    const float* __restrict__ Wm1, const float* __restrict__ Ws1) {
    __shared__ float As[16][68];
    __shared__ float Bs[16][68];
    int m0 = blockIdx.x * 64, n0 = blockIdx.y * 64;
    int z  = blockIdx.z;
    int kbeg = z * 128;
    const float* Wb = (n0 < 256) ? Wm1 : Ws1;
    int nc0 = n0 & 255;

    int tid = threadIdx.x;
    int tx = tid & 15, ty = tid >> 4;
    int alk = tid & 15, alm = tid >> 4;
    int bln = tid & 63, blk = tid >> 6;

    float acc[4][4] = {};
    for (int kk = 0; kk < 128; kk += 16) {
        #pragma unroll
        for (int i = 0; i < 4; i++) {
            int m = alm + i * 16;
            As[alk][m] = g_h[(size_t)(m0 + m) * H_ + kbeg + kk + alk];
        }
        #pragma unroll
        for (int i = 0; i < 4; i++) {
            int kg = kbeg + kk + blk + i * 4;
            Bs[blk + i * 4][bln] = Wb[(size_t)kg * 256 + nc0 + bln];
        }
        __syncthreads();
        #pragma unroll
        for (int q = 0; q < 16; q++) {
            float a[4], b[4];
            *(float4*)a = *(const float4*)&As[q][ty * 4];
            *(float4*)b = *(const float4*)&Bs[q][tx * 4];
            #pragma unroll
            for (int i = 0; i < 4; i++)
                #pragma unroll
                for (int j = 0; j < 4; j++)
                    acc[i][j] = fmaf(a[i], b[j], acc[i][j]);
        }
        __syncthreads();
    }
    float* outp = g_h2part[z];
    #pragma unroll
    for (int i = 0; i < 4; i++)
        #pragma unroll
        for (int j = 0; j < 4; j++)
            outp[(size_t)(m0 + ty * 4 + i) * H_ + n0 + tx * 4 + j] = acc[i][j];
}

// ---------------- heads: reduce gemm2 partials + bias + relu, then
//                  mean = tanh(hm@Wm2+bm2), std = exp(hs@Ws2+bs2), z ----------------
__global__ void head_kernel(const float* __restrict__ bm1, const float* __restrict__ bs1,
                            const float* __restrict__ Wm2, const float* __restrict__ bm2,
                            const float* __restrict__ Ws2, const float* __restrict__ bs2,
                            const float* __restrict__ eps, float* __restrict__ out, int k) {
    __shared__ float sh[H_];
    __shared__ float sred[8];
    int p = blockIdx.x, tid = threadIdx.x;
    for (int i = tid; i < H_; i += 64) {
        float v = (i < 256) ? bm1[i] : bs1[i - 256];
        #pragma unroll
        for (int z = 0; z < 4; z++) v += g_h2part[z][(size_t)p * H_ + i];
        sh[i] = fmaxf(v, 0.f);
    }
    __syncthreads();

    float pm0 = 0, pm1 = 0, ps0 = 0, ps1 = 0;
    for (int i = tid; i < 256; i += 64) {
        float hm = sh[i], hs = sh[256 + i];
        pm0 = fmaf(hm, Wm2[2 * i],     pm0);
        pm1 = fmaf(hm, Wm2[2 * i + 1], pm1);
        ps0 = fmaf(hs, Ws2[2 * i],     ps0);
        ps1 = fmaf(hs, Ws2[2 * i + 1], ps1);
    }
    #pragma unroll
    for (int o = 16; o; o >>= 1) {
        pm0 += __shfl_down_sync(0xffffffffu, pm0, o);
        pm1 += __shfl_down_sync(0xffffffffu, pm1, o);
        ps0 += __shfl_down_sync(0xffffffffu, ps0, o);
        ps1 += __shfl_down_sync(0xffffffffu, ps1, o);
    }
    int warp = tid >> 5, lane = tid & 31;
    if (lane == 0) {
        sred[warp * 4 + 0] = pm0; sred[warp * 4 + 1] = pm1;
        sred[warp * 4 + 2] = ps0; sred[warp * 4 + 3] = ps1;
    }
    __syncthreads();
    if (tid == 0) {
        float m0 = sred[0] + sred[4], m1 = sred[1] + sred[5];
        float s0 = sred[2] + sred[6], s1 = sred[3] + sred[7];
        float mean0 = tanhf(m0 + bm2[0]), mean1 = tanhf(m1 + bm2[1]);
        float std0  = expf(s0 + bs2[0]),  std1  = expf(s1 + bs2[1]);
        float e0 = eps[(p * K_ + k) * 2], e1 = eps[(p * K_ + k) * 2 + 1];
        float z0 = fmaf(std0, e0, mean0), z1 = fmaf(std1, e1, mean1);
        int o = p * 6 + k * 2;
        out[o] = mean0;        out[o + 1] = mean1;          // q_mean
        out[1536 + o] = std0;  out[1536 + o + 1] = std1;    // q_std
        out[3072 + o] = z0;    out[3072 + o + 1] = z1;      // z_where
        g_z[p * 2] = z0; g_z[p * 2 + 1] = z1;
    }
}

// ---------------- recon: bilinear digit placement, subtract from frame_left ----------------
__global__ void recon_kernel(const float* __restrict__ ck, int k) {
    __shared__ float dig[784];
    __shared__ float wx0[96], wx1[96], wy0[96], wy1[96];
    __shared__ int   ix0[96], ix1[96], iy0[96], iy1[96];
    int p = blockIdx.x, tid = threadIdx.x;
    const float* gk = ck + ((size_t)p * K_ + k) * 784;
    for (int i = tid; i < 784; i += 256) dig[i] = gk[i];
    float z0 = g_z[p * 2], z1 = g_z[p * 2 + 1];

    if (tid < 192) {
        int j = tid % 96;
        float zw = (tid < 96) ? z0 : z1;
        const float scale = (float)(96.0 / 28.0);
        float oc = (2.f * j + 1.f) / 96.f - 1.f;
        float pp = ((scale * (oc - zw) + 1.f) * 28.f - 1.f) * 0.5f;
        float p0 = floorf(pp);
        float f  = pp - p0;
        int i0 = (int)p0, i1 = i0 + 1;
        float w0 = (i0 >= 0 && i0 < DPX) ? 1.f - f : 0.f;
        float w1 = (i1 >= 0 && i1 < DPX) ? f : 0.f;
        i0 = min(max(i0, 0), DPX - 1);
        i1 = min(max(i1, 0), DPX - 1);
        if (tid < 96) { wx0[j] = w0; wx1[j] = w1; ix0[j] = i0; ix1[j] = i1; }
        else          { wy0[j] = w0; wy1[j] = w1; iy0[j] = i0; iy1[j] = i1; }
    }
    __syncthreads();

    float* fl = g_frame + (size_t)p * FRPIX;
    for (int idx = tid; idx < FRPIX; idx += 256) {
        int i = idx / 96, j = idx - i * 96;
        float a = wy0[i] * dig[iy0[i] * DPX + ix0[j]] + wy1[i] * dig[iy1[i] * DPX + ix0[j]];
        float b = wy0[i] * dig[iy0[i] * DPX + ix1[j]] + wy1[i] * dig[iy1[i] * DPX + ix1[j]];
        fl[idx] -= (wx0[j] * a + wx1[j] * b);
    }
}

// ---------------- launch ----------------
extern "C" void kernel_launch(void* const* d_in, const int* in_sizes, int n_in,
                              void* d_out, int out_size) {
    const float* frames = (const float*)d_in[0];
    const float* ck     = (const float*)d_in[1];
    const float* eps    = (const float*)d_in[2];
    const float* W1     = (const float*)d_in[3];
    const float* b1     = (const float*)d_in[4];
    const float* Wm1    = (const float*)d_in[5];
    const float* bm1    = (const float*)d_in[6];
    const float* Wm2    = (const float*)d_in[7];
    const float* bm2    = (const float*)d_in[8];
    const float* Ws1    = (const float*)d_in[9];
    const float* bs1    = (const float*)d_in[10];
    const float* Ws2    = (const float*)d_in[11];
    const float* bs2    = (const float*)d_in[12];
    const int*   ts     = (const int*)d_in[13];
    float* out = (float*)d_out;

    const int convSmem = CONV_SMEM_FLOATS * (int)sizeof(float);  // ~59.7 KB
    cudaFuncSetAttribute(conv_softmax_kernel,
                         cudaFuncAttributeMaxDynamicSharedMemorySize, convSmem);

    init_frame_kernel<<<(SB * FRPIX + 255) / 256, 256>>>(frames, ts);

    for (int k = 0; k < K_; k++) {
        conv_softmax_kernel<<<SB, 256, convSmem>>>(ck, k);
        gemm1_kernel<<<dim3(2, 8, 9), 128>>>(W1);
        reduce_relu_kernel<<<128, 256>>>(b1);
        gemm2_kernel<<<dim3(4, 8, 4), 256>>>(Wm1, Ws1);
        head_kernel<<<SB, 64>>>(bm1, bs1, Wm2, bm2, Ws2, bs2, eps, out, k);
        if (k < K_ - 1) recon_kernel<<<SB, 256>>>(ck, k);
    }
}

// round 5
// speedup vs baseline: 1.5904x; 1.1253x over previous
#include <cuda_runtime.h>
#include <cuda_bf16.h>
#include <math.h>
#include <stdint.h>

#define S_   4
#define B_   64
#define K_   3
#define T_   8
#define FPX  96
#define DPX  28
#define CPX  69
#define NPX  4761     // 69*69
#define NPXB 4800     // padded to 75*64 for bf16 tensor path
#define H_   512
#define SB   256      // S_*B_
#define FRPIX 9216    // 96*96

#define ZSPLIT 5
#define KC 64
#define NCH 15        // 960 / 64 chunks per z

// ---------------- scratch (device globals; no allocation allowed) ----------------
__device__ float g_frame[SB * FRPIX];              // residual frame_left
__device__ __nv_bfloat16 g_sAh[SB * NPXB];         // scores hi (bf16), [m][k]
__device__ __nv_bfloat16 g_sAl[SB * NPXB];         // scores lo
__device__ __nv_bfloat16 g_W1h[H_ * NPXB];         // W1^T hi (bf16), [n][k]
__device__ __nv_bfloat16 g_W1l[H_ * NPXB];         // W1^T lo
__device__ float g_hpart[ZSPLIT][SB * H_];         // split-K partials for GEMM1
__device__ float g_h[SB * H_];                     // relu(scores@W1 + b1)
__device__ float g_h2part[4][SB * H_];             // split-K partials for GEMM2
__device__ float g_z[SB * 2];                      // z_where for recon

__device__ __forceinline__ uint32_t smem_u32(const void* p) {
    uint32_t a;
    asm("{ .reg .u64 t; cvta.to.shared.u64 t, %1; cvt.u32.u64 %0, t; }" : "=r"(a) : "l"(p));
    return a;
}

// ---------------- init: frame_left = frames[:, :, timestep] ----------------
__global__ void init_frame_kernel(const float* __restrict__ frames,
                                  const int* __restrict__ ts_p) {
    int idx = blockIdx.x * 256 + threadIdx.x;
    if (idx >= SB * FRPIX) return;
    int ts = *ts_p;
    int p = idx / FRPIX, off = idx % FRPIX;
    g_frame[idx] = frames[(size_t)(p * T_ + ts) * FRPIX + off];
}

// ---------------- once per launch: W1 -> transposed bf16 hi/lo [n][k] ----------------
__global__ void split_W1_kernel(const float* __restrict__ W1) {
    __shared__ float t[32][33];
    int kt = blockIdx.x * 32, nt = blockIdx.y * 32;
    int tx = threadIdx.x, ty = threadIdx.y;   // 32 x 8
    #pragma unroll
    for (int i = 0; i < 32; i += 8) {
        int k = kt + ty + i, n = nt + tx;
        t[ty + i][tx] = (k < NPX) ? W1[(size_t)k * H_ + n] : 0.f;
    }
    __syncthreads();
    #pragma unroll
    for (int i = 0; i < 32; i += 8) {
        int n = nt + ty + i, k = kt + tx;
        float v = t[tx][ty + i];
        __nv_bfloat16 h = __float2bfloat16(v);
        __nv_bfloat16 l = __float2bfloat16(v - __bfloat162float(h));
        g_W1h[(size_t)n * NPXB + k] = h;
        g_W1l[(size_t)n * NPXB + k] = l;
    }
}

// ---------------- fused conv (VALID 96x96 (*) 28x28 -> 69x69) + softmax -> bf16 hi/lo ---
#define SF_STRIDE 97
#define CONV_SMEM_FLOATS (96 * 97 + 40 + 784 + NPX + 32)

__global__ __launch_bounds__(256) void conv_softmax_kernel(
    const float* __restrict__ ck, int k) {
    extern __shared__ float smem[];
    float* sf  = smem;
    float* sk  = sf + 96 * 97 + 40;
    float* ssc = sk + 784;
    float* red = ssc + NPX;

    int p = blockIdx.x;
    int tid = threadIdx.x;

    const float* gf = g_frame + (size_t)p * FRPIX;
    for (int i = tid; i < FRPIX; i += 256) {
        int r = i / FPX, c = i - r * FPX;
        sf[r * SF_STRIDE + c] = gf[i];
    }
    const float* gk = ck + ((size_t)p * K_ + k) * 784;
    for (int i = tid; i < 784; i += 256) sk[i] = gk[i];
    __syncthreads();

    #pragma unroll
    for (int rnd = 0; rnd < 3; rnd++) {
        int u = tid + rnd * 256;
        if (u < 621) {
            int cb = u / 69;
            int r  = u - cb * 69;
            int x0 = cb * 8;
            float acc[8] = {0.f,0.f,0.f,0.f,0.f,0.f,0.f,0.f};
            for (int ky = 0; ky < DPX; ky++) {
                const float* fr = sf + (r + ky) * SF_STRIDE + x0;
                const float* kr = sk + ky * DPX;
                float win[35];
                #pragma unroll
                for (int i = 0; i < 35; i++) win[i] = fr[i];
                #pragma unroll
                for (int kx = 0; kx < DPX; kx++) {
                    float kv = kr[kx];
                    #pragma unroll
                    for (int j = 0; j < 8; j++)
                        acc[j] = fmaf(win[kx + j], kv, acc[j]);
                }
            }
            int nc = min(8, CPX - x0);
            for (int j = 0; j < nc; j++) ssc[r * CPX + x0 + j] = acc[j];
        }
    }
    __syncthreads();

    int warp = tid >> 5, lane = tid & 31;
    float lm = -3.4e38f;
    for (int i = tid; i < NPX; i += 256) lm = fmaxf(lm, ssc[i]);
    #pragma unroll
    for (int o = 16; o; o >>= 1) lm = fmaxf(lm, __shfl_xor_sync(0xffffffffu, lm, o));
    if (lane == 0) red[warp] = lm;
    __syncthreads();
    float M = red[0];
    #pragma unroll
    for (int w = 1; w < 8; w++) M = fmaxf(M, red[w]);
    __syncthreads();

    float ls = 0.f;
    for (int i = tid; i < NPX; i += 256) {
        float e = expf(ssc[i] - M);
        ssc[i] = e;
        ls += e;
    }
    #pragma unroll
    for (int o = 16; o; o >>= 1) ls += __shfl_xor_sync(0xffffffffu, ls, o);
    if (lane == 0) red[warp] = ls;
    __syncthreads();
    float tot = 0.f;
    #pragma unroll
    for (int w = 0; w < 8; w++) tot += red[w];
    float inv = 1.f / tot;

    __nv_bfloat16* gh = g_sAh + (size_t)p * NPXB;
    __nv_bfloat16* gl = g_sAl + (size_t)p * NPXB;
    for (int i = tid; i < NPX; i += 256) {
        float s = ssc[i] * inv;
        __nv_bfloat16 h = __float2bfloat16(s);
        gh[i] = h;
        gl[i] = __float2bfloat16(s - __bfloat162float(h));
    }
    if (tid < NPXB - NPX) {
        gh[NPX + tid] = __float2bfloat16(0.f);
        gl[NPX + tid] = __float2bfloat16(0.f);
    }
}

// ---------------- GEMM1 (mma.sync bf16, 3-term split): scores @ W1^T -------------
// grid (2, 8, ZSPLIT), 128 threads (2x2 warps, 64x32 warp tiles).
// smem: padded rows (stride 72 bf16) -> conflict-free ldmatrix, cp.async pipeline.
#define AST 72
#define BST 72
#define SM_AH(b) ((b) * 9216)
#define SM_AL(b) (18432 + (b) * 9216)
#define SM_BH(b) (36864 + (b) * 4608)
#define SM_BL(b) (46080 + (b) * 4608)
#define GEMM1_SMEM_BYTES (55296 * 2)

#define LDMX4(r0, r1, r2, r3, addr) \
    asm volatile("ldmatrix.sync.aligned.m8n8.x4.shared.b16 {%0,%1,%2,%3}, [%4];" \
                 : "=r"(r0), "=r"(r1), "=r"(r2), "=r"(r3) : "r"(addr))

#define MMA16816(c, a, b0, b1) \
    asm volatile("mma.sync.aligned.m16n8k16.row.col.f32.bf16.bf16.f32 " \
                 "{%0,%1,%2,%3}, {%4,%5,%6,%7}, {%8,%9}, {%0,%1,%2,%3};" \
                 : "+f"((c)[0]), "+f"((c)[1]), "+f"((c)[2]), "+f"((c)[3]) \
                 : "r"((a)[0]), "r"((a)[1]), "r"((a)[2]), "r"((a)[3]), \
                   "r"(b0), "r"(b1))

__global__ __launch_bounds__(128) void gemm1_mma_kernel() {
    extern __shared__ __nv_bfloat16 sm[];
    uint32_t sbase = smem_u32(sm);
    int tid = threadIdx.x;
    int wid = tid >> 5, lane = tid & 31;
    int m0 = blockIdx.x * 128, n0 = blockIdx.y * 64;
    int z = blockIdx.z;
    int kbeg0 = z * 960;
    int wm = (wid >> 1) * 64, wn = (wid & 1) * 32;

    auto prefetch = [&](int buf, int kbeg) {
        #pragma unroll
        for (int t = 0; t < 2; t++) {
            const __nv_bfloat16* src = t ? g_sAl : g_sAh;
            uint32_t dst0 = sbase + (uint32_t)((t ? SM_AL(buf) : SM_AH(buf)) * 2);
            #pragma unroll
            for (int i = 0; i < 8; i++) {
                int u = i * 128 + tid;
                int row = u >> 3, c16 = u & 7;
                const void* g = src + (size_t)(m0 + row) * NPXB + kbeg + c16 * 8;
                uint32_t d = dst0 + (uint32_t)((row * AST + c16 * 8) * 2);
                asm volatile("cp.async.cg.shared.global [%0], [%1], 16;" :: "r"(d), "l"(g));
            }
        }
        #pragma unroll
        for (int t = 0; t < 2; t++) {
            const __nv_bfloat16* src = t ? g_W1l : g_W1h;
            uint32_t dst0 = sbase + (uint32_t)((t ? SM_BL(buf) : SM_BH(buf)) * 2);
            #pragma unroll
            for (int i = 0; i < 4; i++) {
                int u = i * 128 + tid;
                int row = u >> 3, c16 = u & 7;
                const void* g = src + (size_t)(n0 + row) * NPXB + kbeg + c16 * 8;
                uint32_t d = dst0 + (uint32_t)((row * BST + c16 * 8) * 2);
                asm volatile("cp.async.cg.shared.global [%0], [%1], 16;" :: "r"(d), "l"(g));
            }
        }
        asm volatile("cp.async.commit_group;");
    };

    float acc[4][4][4] = {};   // [m16 tile][n8 tile][frag reg]

    prefetch(0, kbeg0);
    asm volatile("cp.async.wait_group 0;");
    __syncthreads();

    for (int ci = 0; ci < NCH; ci++) {
        int buf = ci & 1;
        if (ci + 1 < NCH) prefetch(buf ^ 1, kbeg0 + (ci + 1) * KC);

        uint32_t aH = sbase + (uint32_t)(SM_AH(buf) * 2);
        uint32_t aL = sbase + (uint32_t)(SM_AL(buf) * 2);
        uint32_t bH = sbase + (uint32_t)(SM_BH(buf) * 2);
        uint32_t bL = sbase + (uint32_t)(SM_BL(buf) * 2);

        #pragma unroll
        for (int ks = 0; ks < 4; ks++) {
            int kb = ks * 16;
            uint32_t ah[4][4], al[4][4];
            #pragma unroll
            for (int i = 0; i < 4; i++) {
                uint32_t off = (uint32_t)(((wm + i * 16 + (lane & 15)) * AST
                               + kb + (lane >> 4) * 8) * 2);
                LDMX4(ah[i][0], ah[i][1], ah[i][2], ah[i][3], aH + off);
                LDMX4(al[i][0], al[i][1], al[i][2], al[i][3], aL + off);
            }
            uint32_t bh[4][2], bl[4][2];
            #pragma unroll
            for (int jj = 0; jj < 2; jj++) {
                uint32_t off = (uint32_t)(((wn + jj * 16 + (lane & 15)) * BST
                               + kb + (lane >> 4) * 8) * 2);
                uint32_t r0, r1, r2, r3;
                LDMX4(r0, r1, r2, r3, bH + off);
                bh[jj * 2][0] = r0; bh[jj * 2][1] = r2;
                bh[jj * 2 + 1][0] = r1; bh[jj * 2 + 1][1] = r3;
                LDMX4(r0, r1, r2, r3, bL + off);
                bl[jj * 2][0] = r0; bl[jj * 2][1] = r2;
                bl[jj * 2 + 1][0] = r1; bl[jj * 2 + 1][1] = r3;
            }
            #pragma unroll
            for (int i = 0; i < 4; i++)
                #pragma unroll
                for (int j = 0; j < 4; j++) {
                    MMA16816(acc[i][j], ah[i], bh[j][0], bh[j][1]);
                    MMA16816(acc[i][j], ah[i], bl[j][0], bl[j][1]);
                    MMA16816(acc[i][j], al[i], bh[j][0], bh[j][1]);
                }
        }
        if (ci + 1 < NCH) asm volatile("cp.async.wait_group 0;");
        __syncthreads();
    }

    // epilogue: d frag -> g_hpart[z]
    float* outp = g_hpart[z];
    int r = lane >> 2, c2 = (lane & 3) * 2;
    #pragma unroll
    for (int i = 0; i < 4; i++)
        #pragma unroll
        for (int j = 0; j < 4; j++) {
            int mrow = m0 + wm + i * 16 + r;
            int ncol = n0 + wn + j * 8 + c2;
            *(float2*)&outp[(size_t)mrow * H_ + ncol] =
                make_float2(acc[i][j][0], acc[i][j][1]);
            *(float2*)&outp[(size_t)(mrow + 8) * H_ + ncol] =
                make_float2(acc[i][j][2], acc[i][j][3]);
        }
}

// ---------------- reduce split-K partials + bias + relu (float4) ----------------
__global__ void reduce_relu_kernel(const float* __restrict__ b1) {
    int idx4 = blockIdx.x * 256 + threadIdx.x;      // < 32768
    float4 s = ((const float4*)b1)[idx4 & 127];
    #pragma unroll
    for (int r = 0; r < ZSPLIT; r++) {
        float4 v = ((const float4*)g_hpart[r])[idx4];
        s.x += v.x; s.y += v.y; s.z += v.z; s.w += v.w;
    }
    s.x = fmaxf(s.x, 0.f); s.y = fmaxf(s.y, 0.f);
    s.z = fmaxf(s.z, 0.f); s.w = fmaxf(s.w, 0.f);
    ((float4*)g_h)[idx4] = s;
}

// ---------------- GEMM2: h(256x512) @ [Wm1 | Ws1](512x512), splitK=4 ----------------
__global__ __launch_bounds__(256) void gemm2_kernel(
    const float* __restrict__ Wm1, const float* __restrict__ Ws1) {
    __shared__ float As[16][68];
    __shared__ float Bs[16][68];
    int m0 = blockIdx.x * 64, n0 = blockIdx.y * 64;
    int z  = blockIdx.z;
    int kbeg = z * 128;
    const float* Wb = (n0 < 256) ? Wm1 : Ws1;
    int nc0 = n0 & 255;

    int tid = threadIdx.x;
    int tx = tid & 15, ty = tid >> 4;
    int alk = tid & 15, alm = tid >> 4;
    int bln = tid & 63, blk = tid >> 6;

    float acc[4][4] = {};
    for (int kk = 0; kk < 128; kk += 16) {
        #pragma unroll
        for (int i = 0; i < 4; i++) {
            int m = alm + i * 16;
            As[alk][m] = g_h[(size_t)(m0 + m) * H_ + kbeg + kk + alk];
        }
        #pragma unroll
        for (int i = 0; i < 4; i++) {
            int kg = kbeg + kk + blk + i * 4;
            Bs[blk + i * 4][bln] = Wb[(size_t)kg * 256 + nc0 + bln];
        }
        __syncthreads();
        #pragma unroll
        for (int q = 0; q < 16; q++) {
            float a[4], b[4];
            *(float4*)a = *(const float4*)&As[q][ty * 4];
            *(float4*)b = *(const float4*)&Bs[q][tx * 4];
            #pragma unroll
            for (int i = 0; i < 4; i++)
                #pragma unroll
                for (int j = 0; j < 4; j++)
                    acc[i][j] = fmaf(a[i], b[j], acc[i][j]);
        }
        __syncthreads();
    }
    float* outp = g_h2part[z];
    #pragma unroll
    for (int i = 0; i < 4; i++)
        #pragma unroll
        for (int j = 0; j < 4; j++)
            outp[(size_t)(m0 + ty * 4 + i) * H_ + n0 + tx * 4 + j] = acc[i][j];
}

// ---------------- heads ----------------
__global__ void head_kernel(const float* __restrict__ bm1, const float* __restrict__ bs1,
                            const float* __restrict__ Wm2, const float* __restrict__ bm2,
                            const float* __restrict__ Ws2, const float* __restrict__ bs2,
                            const float* __restrict__ eps, float* __restrict__ out, int k) {
    __shared__ float sh[H_];
    __shared__ float sred[8];
    int p = blockIdx.x, tid = threadIdx.x;
    for (int i = tid; i < H_; i += 64) {
        float v = (i < 256) ? bm1[i] : bs1[i - 256];
        #pragma unroll
        for (int z = 0; z < 4; z++) v += g_h2part[z][(size_t)p * H_ + i];
        sh[i] = fmaxf(v, 0.f);
    }
    __syncthreads();

    float pm0 = 0, pm1 = 0, ps0 = 0, ps1 = 0;
    for (int i = tid; i < 256; i += 64) {
        float hm = sh[i], hs = sh[256 + i];
        pm0 = fmaf(hm, Wm2[2 * i],     pm0);
        pm1 = fmaf(hm, Wm2[2 * i + 1], pm1);
        ps0 = fmaf(hs, Ws2[2 * i],     ps0);
        ps1 = fmaf(hs, Ws2[2 * i + 1], ps1);
    }
    #pragma unroll
    for (int o = 16; o; o >>= 1) {
        pm0 += __shfl_down_sync(0xffffffffu, pm0, o);
        pm1 += __shfl_down_sync(0xffffffffu, pm1, o);
        ps0 += __shfl_down_sync(0xffffffffu, ps0, o);
        ps1 += __shfl_down_sync(0xffffffffu, ps1, o);
    }
    int warp = tid >> 5, lane = tid & 31;
    if (lane == 0) {
        sred[warp * 4 + 0] = pm0; sred[warp * 4 + 1] = pm1;
        sred[warp * 4 + 2] = ps0; sred[warp * 4 + 3] = ps1;
    }
    __syncthreads();
    if (tid == 0) {
        float m0 = sred[0] + sred[4], m1 = sred[1] + sred[5];
        float s0 = sred[2] + sred[6], s1 = sred[3] + sred[7];
        float mean0 = tanhf(m0 + bm2[0]), mean1 = tanhf(m1 + bm2[1]);
        float std0  = expf(s0 + bs2[0]),  std1  = expf(s1 + bs2[1]);
        float e0 = eps[(p * K_ + k) * 2], e1 = eps[(p * K_ + k) * 2 + 1];
        float z0 = fmaf(std0, e0, mean0), z1 = fmaf(std1, e1, mean1);
        int o = p * 6 + k * 2;
        out[o] = mean0;        out[o + 1] = mean1;
        out[1536 + o] = std0;  out[1536 + o + 1] = std1;
        out[3072 + o] = z0;    out[3072 + o + 1] = z1;
        g_z[p * 2] = z0; g_z[p * 2 + 1] = z1;
    }
}

// ---------------- recon: bilinear digit placement, subtract from frame_left ----------------
__global__ void recon_kernel(const float* __restrict__ ck, int k) {
    __shared__ float dig[784];
    __shared__ float wx0[96], wx1[96], wy0[96], wy1[96];
    __shared__ int   ix0[96], ix1[96], iy0[96], iy1[96];
    int p = blockIdx.x, tid = threadIdx.x;
    const float* gk = ck + ((size_t)p * K_ + k) * 784;
    for (int i = tid; i < 784; i += 256) dig[i] = gk[i];
    float z0 = g_z[p * 2], z1 = g_z[p * 2 + 1];

    if (tid < 192) {
        int j = tid % 96;
        float zw = (tid < 96) ? z0 : z1;
        const float scale = (float)(96.0 / 28.0);
        float oc = (2.f * j + 1.f) / 96.f - 1.f;
        float pp = ((scale * (oc - zw) + 1.f) * 28.f - 1.f) * 0.5f;
        float p0 = floorf(pp);
        float f  = pp - p0;
        int i0 = (int)p0, i1 = i0 + 1;
        float w0 = (i0 >= 0 && i0 < DPX) ? 1.f - f : 0.f;
        float w1 = (i1 >= 0 && i1 < DPX) ? f : 0.f;
        i0 = min(max(i0, 0), DPX - 1);
        i1 = min(max(i1, 0), DPX - 1);
        if (tid < 96) { wx0[j] = w0; wx1[j] = w1; ix0[j] = i0; ix1[j] = i1; }
        else          { wy0[j] = w0; wy1[j] = w1; iy0[j] = i0; iy1[j] = i1; }
    }
    __syncthreads();

    float* fl = g_frame + (size_t)p * FRPIX;
    for (int idx = tid; idx < FRPIX; idx += 256) {
        int i = idx / 96, j = idx - i * 96;
        float a = wy0[i] * dig[iy0[i] * DPX + ix0[j]] + wy1[i] * dig[iy1[i] * DPX + ix0[j]];
        float b = wy0[i] * dig[iy0[i] * DPX + ix1[j]] + wy1[i] * dig[iy1[i] * DPX + ix1[j]];
        fl[idx] -= (wx0[j] * a + wx1[j] * b);
    }
}

// ---------------- launch ----------------
extern "C" void kernel_launch(void* const* d_in, const int* in_sizes, int n_in,
                              void* d_out, int out_size) {
    const float* frames = (const float*)d_in[0];
    const float* ck     = (const float*)d_in[1];
    const float* eps    = (const float*)d_in[2];
    const float* W1     = (const float*)d_in[3];
    const float* b1     = (const float*)d_in[4];
    const float* Wm1    = (const float*)d_in[5];
    const float* bm1    = (const float*)d_in[6];
    const float* Wm2    = (const float*)d_in[7];
    const float* bm2    = (const float*)d_in[8];
    const float* Ws1    = (const float*)d_in[9];
    const float* bs1    = (const float*)d_in[10];
    const float* Ws2    = (const float*)d_in[11];
    const float* bs2    = (const float*)d_in[12];
    const int*   ts     = (const int*)d_in[13];
    float* out = (float*)d_out;

    const int convSmem = CONV_SMEM_FLOATS * (int)sizeof(float);
    cudaFuncSetAttribute(conv_softmax_kernel,
                         cudaFuncAttributeMaxDynamicSharedMemorySize, convSmem);
    cudaFuncSetAttribute(gemm1_mma_kernel,
                         cudaFuncAttributeMaxDynamicSharedMemorySize, GEMM1_SMEM_BYTES);

    init_frame_kernel<<<(SB * FRPIX + 255) / 256, 256>>>(frames, ts);
    split_W1_kernel<<<dim3(NPXB / 32, H_ / 32), dim3(32, 8)>>>(W1);

    for (int k = 0; k < K_; k++) {
        conv_softmax_kernel<<<SB, 256, convSmem>>>(ck, k);
        gemm1_mma_kernel<<<dim3(2, 8, ZSPLIT), 128, GEMM1_SMEM_BYTES>>>();
        reduce_relu_kernel<<<128, 256>>>(b1);
        gemm2_kernel<<<dim3(4, 8, 4), 256>>>(Wm1, Ws1);
        head_kernel<<<SB, 64>>>(bm1, bs1, Wm2, bm2, Ws2, bs2, eps, out, k);
        if (k < K_ - 1) recon_kernel<<<SB, 256>>>(ck, k);
    }
}